// round 12
// baseline (speedup 1.0000x reference)
#include <cuda_runtime.h>
#include <cuda_bf16.h>
#include <cuda_fp16.h>
#include <mma.h>
#include <math.h>

using namespace nvcuda;

#define NMAX 50000
#define EMAX 800000
#define DIM 128
#define HEADS 8
#define DK 16

typedef unsigned long long u64;
typedef unsigned int u32;

// ---------------- scratch (static device globals; no allocation) ----------------
__device__ float g_bk_eff[DIM];
__device__ float g_bv_eff[DIM];
__device__ __align__(16) __half g_Qh[NMAX * DIM];
__device__ __align__(16) __half g_Kh[NMAX * DIM];
__device__ __align__(16) __half g_Vh[NMAX * DIM];
__device__ int   g_count[NMAX];     // zero-init at load; self-reset each run
__device__ int   g_scanbuf[NMAX];
__device__ int   g_part[128];
__device__ int   g_rowptr[NMAX + 1];
__device__ int   g_fill[NMAX];
__device__ __align__(16) int g_esrc[EMAX];
// weight images: 4 matrices x {hi,lo}, each 128x128 bf16 row-major [k][n]
__device__ __align__(16) __nv_bfloat16 g_Bimg[4 * 2 * DIM * DIM];

// ---------------- cp.async helpers --------------------------------------------
__device__ __forceinline__ u32 smem_u32(const void* p) {
    u32 a; asm("{ .reg .u64 t; cvta.to.shared.u64 t, %1; cvt.u32.u64 %0, t; }" : "=r"(a) : "l"(p));
    return a;
}
__device__ __forceinline__ void cp16(u32 sdst, const void* gsrc) {
    asm volatile("cp.async.cg.shared.global [%0], [%1], 16;" :: "r"(sdst), "l"(gsrc));
}
#define CP_COMMIT() asm volatile("cp.async.commit_group;" ::: "memory")
#define CP_WAIT0()  asm volatile("cp.async.wait_group 0;" ::: "memory")

// ---------------- smem layout ---------------------------------------------------
#define LDT 136
#define TILE_B (128 * LDT * 2)        // 34816 B per bf16 tile
#define AH_OFF 0
#define AL_OFF TILE_B
#define BH_OFF (2 * TILE_B)
#define BL_OFF (3 * TILE_B)
#define CST_OFF (4 * TILE_B)          // fp32 staging [128][128] = 64 KB
#define SMEM_W_BYTES (4 * TILE_B + 128 * 128 * 4)   // 204800

// ---------------- 1. fold rel matrices + split all weights into bf16 hi/lo ----
__global__ void prep_all(const float* __restrict__ Wq, const float* __restrict__ Wk,
                         const float* __restrict__ Wv, const float* __restrict__ Wa,
                         const float* __restrict__ bk, const float* __restrict__ bv,
                         const float* __restrict__ rel_att, const float* __restrict__ rel_msg) {
    int t = blockIdx.x * 256 + threadIdx.x;
    if (t < 4 * DIM * DIM) {
        int m = t >> 14, idx = t & 16383;
        float v;
        if (m == 0) v = Wq[idx];
        else if (m == 3) v = Wa[idx];
        else {
            const float* W = (m == 1) ? Wk : Wv;
            const float* R = (m == 1) ? rel_att : rel_msg;
            int k = idx >> 7, c = idx & 127;
            int h = c >> 4, j = c & 15;
            float s = 0.f;
#pragma unroll
            for (int i = 0; i < DK; i++)
                s += W[k * DIM + h * DK + i] * R[h * DK * DK + i * DK + j];
            v = s;
        }
        __nv_bfloat16 hi = __float2bfloat16(v);
        __nv_bfloat16 lo = __float2bfloat16(v - __bfloat162float(hi));
        g_Bimg[(m * 2 + 0) * 16384 + idx] = hi;
        g_Bimg[(m * 2 + 1) * 16384 + idx] = lo;
    } else if (t < 4 * DIM * DIM + 2 * DIM) {
        int r = t - 4 * DIM * DIM;
        const float* b = (r < DIM) ? bk : bv;
        const float* R = (r < DIM) ? rel_att : rel_msg;
        float* O       = (r < DIM) ? g_bk_eff : g_bv_eff;
        int c = r & 127;
        int h = c >> 4, j = c & 15;
        float s = 0.f;
#pragma unroll
        for (int i = 0; i < DK; i++)
            s += b[h * DK + i] * R[h * DK * DK + i * DK + j];
        O[c] = s;
    }
}

// ---------------- shared wmma core (device inline) -----------------------------
// Convert fp32 values to bf16 hi/lo smem words.
__device__ __forceinline__ void cvt8(const float* v, u32* hw, u32* lw) {
#pragma unroll
    for (int j = 0; j < 4; j++) {
        __nv_bfloat16 h0 = __float2bfloat16(v[2 * j]);
        __nv_bfloat16 h1 = __float2bfloat16(v[2 * j + 1]);
        __nv_bfloat16 l0 = __float2bfloat16(v[2 * j] - __bfloat162float(h0));
        __nv_bfloat16 l1 = __float2bfloat16(v[2 * j + 1] - __bfloat162float(h1));
        hw[j] = (u32)__bfloat16_as_ushort(h0) | ((u32)__bfloat16_as_ushort(h1) << 16);
        lw[j] = (u32)__bfloat16_as_ushort(l0) | ((u32)__bfloat16_as_ushort(l1) << 16);
    }
}

// mma mainloop + stage into Cst. Caller has synced Ah/Al/Bh/Bl.
__device__ __forceinline__ void wmma_core(char* smem, int wr, int wc) {
    __nv_bfloat16* Ah = (__nv_bfloat16*)(smem + AH_OFF);
    __nv_bfloat16* Al = (__nv_bfloat16*)(smem + AL_OFF);
    __nv_bfloat16* Bh = (__nv_bfloat16*)(smem + BH_OFF);
    __nv_bfloat16* Bl = (__nv_bfloat16*)(smem + BL_OFF);
    float* Cst = (float*)(smem + CST_OFF);

    wmma::fragment<wmma::accumulator, 16, 16, 16, float> acc[2][4];
#pragma unroll
    for (int i = 0; i < 2; i++)
#pragma unroll
        for (int j = 0; j < 4; j++) wmma::fill_fragment(acc[i][j], 0.f);

#pragma unroll
    for (int kb = 0; kb < 8; kb++) {
        int k0 = kb * 16;
        wmma::fragment<wmma::matrix_a, 16, 16, 16, __nv_bfloat16, wmma::row_major> ah[2], al[2];
        wmma::fragment<wmma::matrix_b, 16, 16, 16, __nv_bfloat16, wmma::row_major> bh[4], bl[4];
#pragma unroll
        for (int i = 0; i < 2; i++) {
            int r = wr * 32 + i * 16;
            wmma::load_matrix_sync(ah[i], Ah + r * LDT + k0, LDT);
            wmma::load_matrix_sync(al[i], Al + r * LDT + k0, LDT);
        }
#pragma unroll
        for (int j = 0; j < 4; j++) {
            int c = wc * 64 + j * 16;
            wmma::load_matrix_sync(bh[j], Bh + k0 * LDT + c, LDT);
            wmma::load_matrix_sync(bl[j], Bl + k0 * LDT + c, LDT);
        }
#pragma unroll
        for (int i = 0; i < 2; i++)
#pragma unroll
            for (int j = 0; j < 4; j++) {
                wmma::mma_sync(acc[i][j], ah[i], bh[j], acc[i][j]);
                wmma::mma_sync(acc[i][j], al[i], bh[j], acc[i][j]);
                wmma::mma_sync(acc[i][j], ah[i], bl[j], acc[i][j]);
            }
    }
    __syncthreads();   // Cst free (conversion/Tst reads done by now in callers)
#pragma unroll
    for (int i = 0; i < 2; i++)
#pragma unroll
        for (int j = 0; j < 4; j++)
            wmma::store_matrix_sync(Cst + (wr * 32 + i * 16) * 128 + wc * 64 + j * 16,
                                    acc[i][j], 128, wmma::mem_row_major);
    __syncthreads();
}

// ---------------- 2. QKV GEMM (bf16x3 split, fp16 outputs) ---------------------
__global__ __launch_bounds__(256, 1) void gemm_qkv(
    const float* __restrict__ A, int N,
    const float* __restrict__ b0, const float* __restrict__ b1, const float* __restrict__ b2,
    __half* __restrict__ C0, __half* __restrict__ C1, __half* __restrict__ C2) {
    extern __shared__ char smem[];
    __nv_bfloat16* Ah = (__nv_bfloat16*)(smem + AH_OFF);
    __nv_bfloat16* Al = (__nv_bfloat16*)(smem + AL_OFF);
    float* Cst = (float*)(smem + CST_OFF);
    u32 sb = smem_u32(smem);

    int tid = threadIdx.x;
    int wid = tid >> 5;
    int block_row = blockIdx.x * 128;
    int wr = wid >> 1, wc = wid & 1;
    bool full = (block_row + 128 <= N);

    // prefetch B images for matrix 0
    {
        const uint4* sh0 = (const uint4*)(g_Bimg + 0);
        const uint4* sl0 = sh0 + 2048;
#pragma unroll
        for (int it = 0; it < 8; it++) {
            int i = tid + it * 256;
            u32 off = (i >> 4) * (LDT * 2) + (i & 15) * 16;
            cp16(sb + BH_OFF + off, sh0 + i);
            cp16(sb + BL_OFF + off, sl0 + i);
        }
        CP_COMMIT();
    }

    // convert A tile fp32 -> bf16 hi/lo
#pragma unroll
    for (int it = 0; it < 8; it++) {
        int chunk = tid + it * 256;
        int row = chunk >> 4;
        int c8 = (chunk & 15) << 3;
        int grow = block_row + row;
        float v[8];
        if (full || grow < N) {
            float4 a0 = *(const float4*)&A[grow * DIM + c8];
            float4 a1 = *(const float4*)&A[grow * DIM + c8 + 4];
            v[0]=a0.x; v[1]=a0.y; v[2]=a0.z; v[3]=a0.w;
            v[4]=a1.x; v[5]=a1.y; v[6]=a1.z; v[7]=a1.w;
        } else {
#pragma unroll
            for (int j = 0; j < 8; j++) v[j] = 0.f;
        }
        u32 hw[4], lw[4];
        cvt8(v, hw, lw);
        *(uint4*)((char*)Ah + row * (LDT * 2) + c8 * 2) = make_uint4(hw[0], hw[1], hw[2], hw[3]);
        *(uint4*)((char*)Al + row * (LDT * 2) + c8 * 2) = make_uint4(lw[0], lw[1], lw[2], lw[3]);
    }

    const float* biases[3] = {b0, b1, b2};
    __half* Cs[3] = {C0, C1, C2};

    for (int m = 0; m < 3; m++) {
        CP_WAIT0();
        __syncthreads();

        wmma_core(smem, wr, wc);

        // prefetch next matrix's B during epilogue
        if (m + 1 < 3) {
            const uint4* shn = (const uint4*)(g_Bimg + (m + 1) * 2 * 16384);
            const uint4* sln = shn + 2048;
#pragma unroll
            for (int it = 0; it < 8; it++) {
                int i = tid + it * 256;
                u32 off = (i >> 4) * (LDT * 2) + (i & 15) * 16;
                cp16(sb + BH_OFF + off, shn + i);
                cp16(sb + BL_OFF + off, sln + i);
            }
            CP_COMMIT();
        }

        const float* bias = biases[m];
        __half* C = Cs[m];
#pragma unroll
        for (int it = 0; it < 16; it++) {
            int s = tid + it * 256;
            int row = s >> 5;
            int col = (s & 31) * 4;
            int grow = block_row + row;
            if (full || grow < N) {
                float4 r = *(float4*)&Cst[row * 128 + col];
                r.x += bias[col + 0]; r.y += bias[col + 1];
                r.z += bias[col + 2]; r.w += bias[col + 3];
                union { uint2 u; __half2 h[2]; } pk;
                pk.h[0] = __floats2half2_rn(r.x, r.y);
                pk.h[1] = __floats2half2_rn(r.z, r.w);
                *(uint2*)&C[grow * DIM + col] = pk.u;
            }
        }
        if (m + 1 < 3) __syncthreads();
    }
}

// ---------------- 3. CSR build --------------------------------------------------
__global__ void count_kernel(const int* __restrict__ dst, int E) {
    int t = blockIdx.x * blockDim.x + threadIdx.x;
    if (t < E) atomicAdd(&g_count[dst[t]], 1);
}

#define SCAN_B 512
__global__ __launch_bounds__(SCAN_B) void scan_phase1(int N) {
    __shared__ int sh[SCAN_B];
    int i = blockIdx.x * SCAN_B + threadIdx.x;
    int v = (i < N) ? g_count[i] : 0;
    sh[threadIdx.x] = v;
    __syncthreads();
#pragma unroll
    for (int off = 1; off < SCAN_B; off <<= 1) {
        int add = (threadIdx.x >= off) ? sh[threadIdx.x - off] : 0;
        __syncthreads();
        sh[threadIdx.x] += add;
        __syncthreads();
    }
    if (i < N) g_scanbuf[i] = sh[threadIdx.x];
    if (threadIdx.x == SCAN_B - 1) g_part[blockIdx.x] = sh[SCAN_B - 1];
}
// phase 3 also resets g_count for the next graph replay (zero-invariant).
__global__ __launch_bounds__(SCAN_B) void scan_phase3(int N, int E, int nsb) {
    __shared__ int sh[128];
    int t = threadIdx.x;
    if (t < 128) sh[t] = (t < nsb) ? g_part[t] : 0;
    __syncthreads();
#pragma unroll
    for (int off = 1; off < 128; off <<= 1) {
        int add = (t < 128 && t >= off) ? sh[t - off] : 0;
        __syncthreads();
        if (t < 128) sh[t] += add;
        __syncthreads();
    }
    int boff = sh[blockIdx.x] - g_part[blockIdx.x];
    int i = blockIdx.x * SCAN_B + t;
    if (i < N) {
        int cnt = g_count[i];
        int r = boff + g_scanbuf[i] - cnt;
        g_rowptr[i] = r;
        g_fill[i] = r;
        g_count[i] = 0;             // self-reset for next run
    }
    if (i == 0) g_rowptr[N] = E;
}
__global__ void scatter_kernel(const int* __restrict__ src, const int* __restrict__ dst, int E) {
    int t = blockIdx.x * blockDim.x + threadIdx.x;
    if (t < E) {
        int pos = atomicAdd(&g_fill[dst[t]], 1);
        g_esrc[pos] = src[t];
    }
}

// ---------------- 4. per-node aggregation (device inline) -----------------------
__device__ __forceinline__ float4 agg_node(int n, int lane, float pri) {
    int beg = g_rowptr[n], end = g_rowptr[n + 1];
    if (beg >= end) return make_float4(0.f, 0.f, 0.f, 0.f);

    uint2 qu = *(const uint2*)&g_Qh[n * DIM + lane * 4];
    float2 q01 = __half22float2(((const __half2*)&qu)[0]);
    float2 q23 = __half22float2(((const __half2*)&qu)[1]);

    float ax0 = 0.f, ay0 = 0.f, az0 = 0.f, aw0 = 0.f, ws0 = 0.f;
    float ax1 = 0.f, ay1 = 0.f, az1 = 0.f, aw1 = 0.f, ws1 = 0.f;

    int p = beg;
    for (; p < end && (p & 3); p++) {
        int sv = g_esrc[p];
        uint2 ku = *(const uint2*)&g_Kh[sv * DIM + lane * 4];
        uint2 vu = *(const uint2*)&g_Vh[sv * DIM + lane * 4];
        float2 k01 = __half22float2(((const __half2*)&ku)[0]);
        float2 k23 = __half22float2(((const __half2*)&ku)[1]);
        float d = q01.x * k01.x + q01.y * k01.y + q23.x * k23.x + q23.y * k23.y;
        d += __shfl_xor_sync(0xffffffffu, d, 1);
        d += __shfl_xor_sync(0xffffffffu, d, 2);
        float w = __expf(d * pri);
        ws0 += w;
        float2 v01 = __half22float2(((const __half2*)&vu)[0]);
        float2 v23 = __half22float2(((const __half2*)&vu)[1]);
        ax0 += w * v01.x; ay0 += w * v01.y; az0 += w * v23.x; aw0 += w * v23.y;
    }
    for (; p + 3 < end; p += 4) {
        int4 s4 = *(const int4*)&g_esrc[p];
        int sv[4] = {s4.x, s4.y, s4.z, s4.w};
        uint2 kk[4], vk[4];
#pragma unroll
        for (int u = 0; u < 4; u++) kk[u] = *(const uint2*)&g_Kh[sv[u] * DIM + lane * 4];
#pragma unroll
        for (int u = 0; u < 4; u++) vk[u] = *(const uint2*)&g_Vh[sv[u] * DIM + lane * 4];
        float d[4];
#pragma unroll
        for (int u = 0; u < 4; u++) {
            float2 k01 = __half22float2(((const __half2*)&kk[u])[0]);
            float2 k23 = __half22float2(((const __half2*)&kk[u])[1]);
            d[u] = q01.x * k01.x + q01.y * k01.y + q23.x * k23.x + q23.y * k23.y;
        }
#pragma unroll
        for (int u = 0; u < 4; u++) d[u] += __shfl_xor_sync(0xffffffffu, d[u], 1);
#pragma unroll
        for (int u = 0; u < 4; u++) d[u] += __shfl_xor_sync(0xffffffffu, d[u], 2);
        float w[4];
#pragma unroll
        for (int u = 0; u < 4; u++) w[u] = __expf(d[u] * pri);
        ws0 += w[0] + w[2];
        ws1 += w[1] + w[3];
#pragma unroll
        for (int u = 0; u < 4; u++) {
            float2 v01 = __half22float2(((const __half2*)&vk[u])[0]);
            float2 v23 = __half22float2(((const __half2*)&vk[u])[1]);
            if (u & 1) {
                ax1 += w[u] * v01.x; ay1 += w[u] * v01.y;
                az1 += w[u] * v23.x; aw1 += w[u] * v23.y;
            } else {
                ax0 += w[u] * v01.x; ay0 += w[u] * v01.y;
                az0 += w[u] * v23.x; aw0 += w[u] * v23.y;
            }
        }
    }
    for (; p < end; p++) {
        int sv = g_esrc[p];
        uint2 ku = *(const uint2*)&g_Kh[sv * DIM + lane * 4];
        uint2 vu = *(const uint2*)&g_Vh[sv * DIM + lane * 4];
        float2 k01 = __half22float2(((const __half2*)&ku)[0]);
        float2 k23 = __half22float2(((const __half2*)&ku)[1]);
        float d = q01.x * k01.x + q01.y * k01.y + q23.x * k23.x + q23.y * k23.y;
        d += __shfl_xor_sync(0xffffffffu, d, 1);
        d += __shfl_xor_sync(0xffffffffu, d, 2);
        float w = __expf(d * pri);
        ws0 += w;
        float2 v01 = __half22float2(((const __half2*)&vu)[0]);
        float2 v23 = __half22float2(((const __half2*)&vu)[1]);
        ax0 += w * v01.x; ay0 += w * v01.y; az0 += w * v23.x; aw0 += w * v23.y;
    }
    float inv = 1.f / (ws0 + ws1);
    return make_float4((ax0 + ax1) * inv, (ay0 + ay1) * inv,
                       (az0 + az1) * inv, (aw0 + aw1) * inv);
}

// ---------------- 5. FUSED aggregate + output GEMM + blend ----------------------
__global__ __launch_bounds__(256, 1) void agg_gemm(
    const float* __restrict__ rel_pri, int N,
    const float* __restrict__ ba, float* __restrict__ out,
    const float* __restrict__ Hin, const float* __restrict__ skip) {
    extern __shared__ char smem[];
    __nv_bfloat16* Ah = (__nv_bfloat16*)(smem + AH_OFF);
    __nv_bfloat16* Al = (__nv_bfloat16*)(smem + AL_OFF);
    float* Tst = (float*)(smem + CST_OFF);   // aggregation result, then C staging
    u32 sb = smem_u32(smem);

    int tid = threadIdx.x;
    int wid = tid >> 5, lane = tid & 31;
    int block_row = blockIdx.x * 128;
    int wr = wid >> 1, wc = wid & 1;
    bool full = (block_row + 128 <= N);

    // prefetch Wa hi/lo images (m=3) — hides under aggregation
    {
        const uint4* sh3 = (const uint4*)(g_Bimg + 3 * 2 * 16384);
        const uint4* sl3 = sh3 + 2048;
#pragma unroll
        for (int it = 0; it < 8; it++) {
            int i = tid + it * 256;
            u32 off = (i >> 4) * (LDT * 2) + (i & 15) * 16;
            cp16(sb + BH_OFF + off, sh3 + i);
            cp16(sb + BL_OFF + off, sl3 + i);
        }
        CP_COMMIT();
    }

    // ---- aggregation: warp w owns local rows [w*16, w*16+16) ----
    float pri = rel_pri[lane >> 2] * 0.25f;
#pragma unroll 1
    for (int i = 0; i < 16; i++) {
        int lrow = wid * 16 + i;
        int n = block_row + lrow;
        float4 r = (n < N) ? agg_node(n, lane, pri) : make_float4(0.f, 0.f, 0.f, 0.f);
        *(float4*)&Tst[lrow * 128 + lane * 4] = r;
    }
    __syncthreads();   // Tst complete

    // ---- convert Tst (smem fp32) -> Ah/Al bf16 hi/lo ----
#pragma unroll
    for (int it = 0; it < 8; it++) {
        int chunk = tid + it * 256;
        int row = chunk >> 4;
        int c8 = (chunk & 15) << 3;
        float v[8];
        float4 a0 = *(float4*)&Tst[row * 128 + c8];
        float4 a1 = *(float4*)&Tst[row * 128 + c8 + 4];
        v[0]=a0.x; v[1]=a0.y; v[2]=a0.z; v[3]=a0.w;
        v[4]=a1.x; v[5]=a1.y; v[6]=a1.z; v[7]=a1.w;
        u32 hw[4], lw[4];
        cvt8(v, hw, lw);
        *(uint4*)((char*)Ah + row * (LDT * 2) + c8 * 2) = make_uint4(hw[0], hw[1], hw[2], hw[3]);
        *(uint4*)((char*)Al + row * (LDT * 2) + c8 * 2) = make_uint4(lw[0], lw[1], lw[2], lw[3]);
    }
    CP_WAIT0();
    __syncthreads();   // Ah/Al + B copies visible to all; Tst reads done

    // ---- output projection (wmma core stages into Tst) ----
    wmma_core(smem, wr, wc);

    // ---- epilogue: bias + sigmoid-skip blend, fp32 out ----
    float sg = 1.f / (1.f + __expf(-skip[0]));
    float alpha = sg, beta = 1.f - sg;
#pragma unroll
    for (int it = 0; it < 16; it++) {
        int s = tid + it * 256;
        int row = s >> 5;
        int col = (s & 31) * 4;
        int grow = block_row + row;
        if (full || grow < N) {
            float4 r = *(float4*)&Tst[row * 128 + col];
            r.x += ba[col + 0]; r.y += ba[col + 1];
            r.z += ba[col + 2]; r.w += ba[col + 3];
            float4 hv = *(const float4*)&Hin[grow * DIM + col];
            r.x = r.x * alpha + hv.x * beta;
            r.y = r.y * alpha + hv.y * beta;
            r.z = r.z * alpha + hv.z * beta;
            r.w = r.w * alpha + hv.w * beta;
            *(float4*)&out[grow * DIM + col] = r;
        }
    }
}

// ---------------- launch ------------------------------------------------------
extern "C" void kernel_launch(void* const* d_in, const int* in_sizes, int n_in,
                              void* d_out, int out_size) {
    const float* h       = (const float*)d_in[0];
    const int*   src     = (const int*)d_in[1];
    const int*   dst     = (const int*)d_in[2];
    const float* Wk      = (const float*)d_in[3];
    const float* bk      = (const float*)d_in[4];
    const float* Wq      = (const float*)d_in[5];
    const float* bq      = (const float*)d_in[6];
    const float* Wv      = (const float*)d_in[7];
    const float* bv      = (const float*)d_in[8];
    const float* Wa      = (const float*)d_in[9];
    const float* ba      = (const float*)d_in[10];
    const float* rel_att = (const float*)d_in[11];
    const float* rel_msg = (const float*)d_in[12];
    const float* rel_pri = (const float*)d_in[13];
    const float* skip    = (const float*)d_in[14];
    float* out = (float*)d_out;

    int N = in_sizes[0] / DIM;
    int E = in_sizes[1];

    void *pbk_eff, *pbv_eff, *pQh, *pKh, *pVh;
    cudaGetSymbolAddress(&pbk_eff, g_bk_eff);
    cudaGetSymbolAddress(&pbv_eff, g_bv_eff);
    cudaGetSymbolAddress(&pQh, g_Qh);
    cudaGetSymbolAddress(&pKh, g_Kh);
    cudaGetSymbolAddress(&pVh, g_Vh);

    cudaFuncSetAttribute(gemm_qkv, cudaFuncAttributeMaxDynamicSharedMemorySize, SMEM_W_BYTES);
    cudaFuncSetAttribute(agg_gemm, cudaFuncAttributeMaxDynamicSharedMemorySize, SMEM_W_BYTES);

    static cudaStream_t s2 = nullptr;
    static cudaEvent_t evFork = nullptr, evJoin = nullptr;
    if (!s2) {
        cudaStreamCreateWithFlags(&s2, cudaStreamNonBlocking);
        cudaEventCreateWithFlags(&evFork, cudaEventDisableTiming);
        cudaEventCreateWithFlags(&evJoin, cudaEventDisableTiming);
    }

    int gb = (N + 127) / 128;
    int nsb = (N + SCAN_B - 1) / SCAN_B;

    // ---- fork ----
    cudaEventRecord(evFork, 0);
    cudaStreamWaitEvent(s2, evFork, 0);

    // branch B (s2): CSR build (g_count self-resets each run)
    count_kernel<<<(E + 255) / 256, 256, 0, s2>>>(dst, E);
    scan_phase1<<<nsb, SCAN_B, 0, s2>>>(N);
    scan_phase3<<<nsb, SCAN_B, 0, s2>>>(N, E, nsb);
    scatter_kernel<<<(E + 255) / 256, 256, 0, s2>>>(src, dst, E);
    cudaEventRecord(evJoin, s2);

    // branch A (stream 0): fused weight prep + Q/K/V projections
    prep_all<<<(4 * DIM * DIM + 2 * DIM + 255) / 256, 256>>>(Wq, Wk, Wv, Wa, bk, bv, rel_att, rel_msg);
    gemm_qkv<<<gb, 256, SMEM_W_BYTES>>>(h, N,
        bq, (const float*)pbk_eff, (const float*)pbv_eff,
        (__half*)pQh, (__half*)pKh, (__half*)pVh);

    // ---- join ----
    cudaStreamWaitEvent(0, evJoin, 0);

    // fused aggregate + output projection + blend
    agg_gemm<<<gb, 256, SMEM_W_BYTES>>>(rel_pri, N, ba, out, h, skip);
}

// round 13
// speedup vs baseline: 1.5110x; 1.5110x over previous
#include <cuda_runtime.h>
#include <cuda_bf16.h>
#include <cuda_fp16.h>
#include <mma.h>
#include <math.h>

using namespace nvcuda;

#define NMAX 50000
#define EMAX 800000
#define DIM 128
#define HEADS 8
#define DK 16

typedef unsigned long long u64;
typedef unsigned int u32;

// ---------------- scratch (static device globals; no allocation) ----------------
__device__ float g_bk_eff[DIM];
__device__ float g_bv_eff[DIM];
__device__ __align__(16) __half g_Qh[NMAX * DIM];
__device__ __align__(16) __half g_Kh[NMAX * DIM];
__device__ __align__(16) __half g_Vh[NMAX * DIM];
__device__ float g_T[NMAX * DIM];
__device__ int   g_count[NMAX];     // zero-init at load; self-reset each run
__device__ int   g_scanbuf[NMAX];
__device__ int   g_part[128];
__device__ int   g_rowptr[NMAX + 1];
__device__ int   g_fill[NMAX];
__device__ __align__(16) int g_esrc[EMAX];
// weight images: 4 matrices x {hi,lo}, each 128x128 bf16 row-major [k][n]
__device__ __align__(16) __nv_bfloat16 g_Bimg[4 * 2 * DIM * DIM];

// ---------------- cp.async helpers --------------------------------------------
__device__ __forceinline__ u32 smem_u32(const void* p) {
    u32 a; asm("{ .reg .u64 t; cvta.to.shared.u64 t, %1; cvt.u32.u64 %0, t; }" : "=r"(a) : "l"(p));
    return a;
}
__device__ __forceinline__ void cp16(u32 sdst, const void* gsrc) {
    asm volatile("cp.async.cg.shared.global [%0], [%1], 16;" :: "r"(sdst), "l"(gsrc));
}
#define CP_COMMIT() asm volatile("cp.async.commit_group;" ::: "memory")
#define CP_WAIT0()  asm volatile("cp.async.wait_group 0;" ::: "memory")

// ---------------- 1. fold rel matrices + split all weights into bf16 hi/lo ----
__global__ void prep_all(const float* __restrict__ Wq, const float* __restrict__ Wk,
                         const float* __restrict__ Wv, const float* __restrict__ Wa,
                         const float* __restrict__ bk, const float* __restrict__ bv,
                         const float* __restrict__ rel_att, const float* __restrict__ rel_msg) {
    int t = blockIdx.x * 256 + threadIdx.x;
    if (t < 4 * DIM * DIM) {
        int m = t >> 14, idx = t & 16383;
        float v;
        if (m == 0) v = Wq[idx];
        else if (m == 3) v = Wa[idx];
        else {
            const float* W = (m == 1) ? Wk : Wv;
            const float* R = (m == 1) ? rel_att : rel_msg;
            int k = idx >> 7, c = idx & 127;
            int h = c >> 4, j = c & 15;
            float s = 0.f;
#pragma unroll
            for (int i = 0; i < DK; i++)
                s += W[k * DIM + h * DK + i] * R[h * DK * DK + i * DK + j];
            v = s;
        }
        __nv_bfloat16 hi = __float2bfloat16(v);
        __nv_bfloat16 lo = __float2bfloat16(v - __bfloat162float(hi));
        g_Bimg[(m * 2 + 0) * 16384 + idx] = hi;
        g_Bimg[(m * 2 + 1) * 16384 + idx] = lo;
    } else if (t < 4 * DIM * DIM + 2 * DIM) {
        int r = t - 4 * DIM * DIM;
        const float* b = (r < DIM) ? bk : bv;
        const float* R = (r < DIM) ? rel_att : rel_msg;
        float* O       = (r < DIM) ? g_bk_eff : g_bv_eff;
        int c = r & 127;
        int h = c >> 4, j = c & 15;
        float s = 0.f;
#pragma unroll
        for (int i = 0; i < DK; i++)
            s += b[h * DK + i] * R[h * DK * DK + i * DK + j];
        O[c] = s;
    }
}

// ---------------- 2. wmma bf16x3-split GEMM (cp.async pipelined B) ------------
#define LDT 136
#define TILE_B (128 * LDT * 2)        // 34816 B
#define AH_OFF 0
#define AL_OFF TILE_B
#define BH_OFF (2 * TILE_B)
#define BL_OFF (3 * TILE_B)
#define CST_OFF (4 * TILE_B)          // separate fp32 staging
#define SMEM_W_BYTES (4 * TILE_B + 128 * 128 * 4)   // 204800

__global__ __launch_bounds__(256, 1) void gemm_wmma(
    const float* __restrict__ A, int N, int mstart, int nmat,
    const float* __restrict__ b0, const float* __restrict__ b1, const float* __restrict__ b2,
    float* __restrict__ C0, float* __restrict__ C1, float* __restrict__ C2,
    int halfbits, int blend, const float* __restrict__ Hin, const float* __restrict__ skip) {
    extern __shared__ char smem[];
    __nv_bfloat16* Ah = (__nv_bfloat16*)(smem + AH_OFF);
    __nv_bfloat16* Al = (__nv_bfloat16*)(smem + AL_OFF);
    __nv_bfloat16* Bh = (__nv_bfloat16*)(smem + BH_OFF);
    __nv_bfloat16* Bl = (__nv_bfloat16*)(smem + BL_OFF);
    float* Cst = (float*)(smem + CST_OFF);
    u32 sb = smem_u32(smem);

    int tid = threadIdx.x;
    int wid = tid >> 5;
    int block_row = blockIdx.x * 128;
    int wr = wid >> 1;
    int wc = wid & 1;

    // ---- prefetch B images for matrix 0 (overlaps A conversion) ----
    {
        const uint4* sh0 = (const uint4*)(g_Bimg + mstart * 2 * 16384);
        const uint4* sl0 = sh0 + 2048;
#pragma unroll
        for (int it = 0; it < 8; it++) {
            int i = tid + it * 256;
            int row = i >> 4, c16 = i & 15;
            u32 off = row * (LDT * 2) + c16 * 16;
            cp16(sb + BH_OFF + off, sh0 + i);
            cp16(sb + BL_OFF + off, sl0 + i);
        }
        CP_COMMIT();
    }

    // ---- convert A tile fp32 -> bf16 hi/lo into padded smem ----
    bool full = (block_row + 128 <= N);
#pragma unroll
    for (int it = 0; it < 8; it++) {
        int chunk = tid + it * 256;
        int row = chunk >> 4;
        int c8 = (chunk & 15) << 3;
        int grow = block_row + row;
        float4 a0, a1;
        if (full || grow < N) {
            a0 = *(const float4*)&A[grow * DIM + c8];
            a1 = *(const float4*)&A[grow * DIM + c8 + 4];
        } else {
            a0 = make_float4(0.f, 0.f, 0.f, 0.f); a1 = a0;
        }
        float v[8] = {a0.x, a0.y, a0.z, a0.w, a1.x, a1.y, a1.z, a1.w};
        u32 hw[4], lw[4];
#pragma unroll
        for (int j = 0; j < 4; j++) {
            __nv_bfloat16 h0 = __float2bfloat16(v[2 * j]);
            __nv_bfloat16 h1 = __float2bfloat16(v[2 * j + 1]);
            __nv_bfloat16 l0 = __float2bfloat16(v[2 * j] - __bfloat162float(h0));
            __nv_bfloat16 l1 = __float2bfloat16(v[2 * j + 1] - __bfloat162float(h1));
            hw[j] = (u32)__bfloat16_as_ushort(h0) | ((u32)__bfloat16_as_ushort(h1) << 16);
            lw[j] = (u32)__bfloat16_as_ushort(l0) | ((u32)__bfloat16_as_ushort(l1) << 16);
        }
        *(uint4*)((char*)Ah + row * (LDT * 2) + c8 * 2) = make_uint4(hw[0], hw[1], hw[2], hw[3]);
        *(uint4*)((char*)Al + row * (LDT * 2) + c8 * 2) = make_uint4(lw[0], lw[1], lw[2], lw[3]);
    }

    const float* biases[3] = {b0, b1, b2};
    float* Cs[3] = {C0, C1, C2};

    for (int m = 0; m < nmat; m++) {
        CP_WAIT0();
        __syncthreads();            // B copy done + (m==0) A conversion visible

        wmma::fragment<wmma::accumulator, 16, 16, 16, float> acc[2][4];
#pragma unroll
        for (int i = 0; i < 2; i++)
#pragma unroll
            for (int j = 0; j < 4; j++) wmma::fill_fragment(acc[i][j], 0.f);

#pragma unroll
        for (int kb = 0; kb < 8; kb++) {
            int k0 = kb * 16;
            wmma::fragment<wmma::matrix_a, 16, 16, 16, __nv_bfloat16, wmma::row_major> ah[2], al[2];
            wmma::fragment<wmma::matrix_b, 16, 16, 16, __nv_bfloat16, wmma::row_major> bh[4], bl[4];
#pragma unroll
            for (int i = 0; i < 2; i++) {
                int r = wr * 32 + i * 16;
                wmma::load_matrix_sync(ah[i], Ah + r * LDT + k0, LDT);
                wmma::load_matrix_sync(al[i], Al + r * LDT + k0, LDT);
            }
#pragma unroll
            for (int j = 0; j < 4; j++) {
                int c = wc * 64 + j * 16;
                wmma::load_matrix_sync(bh[j], Bh + k0 * LDT + c, LDT);
                wmma::load_matrix_sync(bl[j], Bl + k0 * LDT + c, LDT);
            }
#pragma unroll
            for (int i = 0; i < 2; i++)
#pragma unroll
                for (int j = 0; j < 4; j++) {
                    wmma::mma_sync(acc[i][j], ah[i], bh[j], acc[i][j]);
                    wmma::mma_sync(acc[i][j], al[i], bh[j], acc[i][j]);
                    wmma::mma_sync(acc[i][j], ah[i], bl[j], acc[i][j]);
                }
        }
        __syncthreads();            // everyone done reading B

        // ---- prefetch next matrix's B while we do the epilogue ----
        if (m + 1 < nmat) {
            const uint4* shn = (const uint4*)(g_Bimg + (mstart + m + 1) * 2 * 16384);
            const uint4* sln = shn + 2048;
#pragma unroll
            for (int it = 0; it < 8; it++) {
                int i = tid + it * 256;
                int row = i >> 4, c16 = i & 15;
                u32 off = row * (LDT * 2) + c16 * 16;
                cp16(sb + BH_OFF + off, shn + i);
                cp16(sb + BL_OFF + off, sln + i);
            }
            CP_COMMIT();
        }

        // ---- stage C, then bias/blend/store ----
#pragma unroll
        for (int i = 0; i < 2; i++)
#pragma unroll
            for (int j = 0; j < 4; j++)
                wmma::store_matrix_sync(Cst + (wr * 32 + i * 16) * 128 + wc * 64 + j * 16,
                                        acc[i][j], 128, wmma::mem_row_major);
        __syncthreads();

        float alpha = 1.f, beta = 0.f;
        if (blend) {
            float sg = 1.f / (1.f + __expf(-skip[0]));
            alpha = sg; beta = 1.f - sg;
        }
        const float* bias = biases[m];
        float* C = Cs[m];
        int ashalf = (halfbits >> m) & 1;
#pragma unroll
        for (int it = 0; it < 16; it++) {
            int s = tid + it * 256;
            int row = s >> 5;
            int col = (s & 31) * 4;
            int grow = block_row + row;
            if (full || grow < N) {
                float4 r = *(float4*)&Cst[row * 128 + col];
                r.x += bias[col + 0]; r.y += bias[col + 1];
                r.z += bias[col + 2]; r.w += bias[col + 3];
                if (blend) {
                    float4 hv = *(const float4*)&Hin[grow * DIM + col];
                    r.x = r.x * alpha + hv.x * beta;
                    r.y = r.y * alpha + hv.y * beta;
                    r.z = r.z * alpha + hv.z * beta;
                    r.w = r.w * alpha + hv.w * beta;
                }
                if (ashalf) {
                    __half* Ch = (__half*)C;
                    union { uint2 u; __half2 h[2]; } pk;
                    pk.h[0] = __floats2half2_rn(r.x, r.y);
                    pk.h[1] = __floats2half2_rn(r.z, r.w);
                    *(uint2*)&Ch[grow * DIM + col] = pk.u;
                } else {
                    *(float4*)&C[grow * DIM + col] = r;
                }
            }
        }
        if (m + 1 < nmat) __syncthreads();   // Cst reuse barrier
    }
}

// ---------------- 3. CSR build --------------------------------------------------
__global__ void count_kernel(const int* __restrict__ dst, int E) {
    int t = blockIdx.x * blockDim.x + threadIdx.x;
    if (t < E) atomicAdd(&g_count[dst[t]], 1);
}

#define SCAN_B 512
__global__ __launch_bounds__(SCAN_B) void scan_phase1(int N) {
    __shared__ int sh[SCAN_B];
    int i = blockIdx.x * SCAN_B + threadIdx.x;
    int v = (i < N) ? g_count[i] : 0;
    sh[threadIdx.x] = v;
    __syncthreads();
#pragma unroll
    for (int off = 1; off < SCAN_B; off <<= 1) {
        int add = (threadIdx.x >= off) ? sh[threadIdx.x - off] : 0;
        __syncthreads();
        sh[threadIdx.x] += add;
        __syncthreads();
    }
    if (i < N) g_scanbuf[i] = sh[threadIdx.x];
    if (threadIdx.x == SCAN_B - 1) g_part[blockIdx.x] = sh[SCAN_B - 1];
}
// phase 3 also resets g_count for the next graph replay (zero-invariant).
__global__ __launch_bounds__(SCAN_B) void scan_phase3(int N, int E, int nsb) {
    __shared__ int sh[128];
    int t = threadIdx.x;
    if (t < 128) sh[t] = (t < nsb) ? g_part[t] : 0;
    __syncthreads();
#pragma unroll
    for (int off = 1; off < 128; off <<= 1) {
        int add = (t < 128 && t >= off) ? sh[t - off] : 0;
        __syncthreads();
        if (t < 128) sh[t] += add;
        __syncthreads();
    }
    int boff = sh[blockIdx.x] - g_part[blockIdx.x];
    int i = blockIdx.x * SCAN_B + t;
    if (i < N) {
        int cnt = g_count[i];
        int r = boff + g_scanbuf[i] - cnt;
        g_rowptr[i] = r;
        g_fill[i] = r;
        g_count[i] = 0;             // self-reset for next run
    }
    if (i == 0) g_rowptr[N] = E;
}
__global__ void scatter_kernel(const int* __restrict__ src, const int* __restrict__ dst, int E) {
    int t = blockIdx.x * blockDim.x + threadIdx.x;
    if (t < E) {
        int pos = atomicAdd(&g_fill[dst[t]], 1);
        g_esrc[pos] = src[t];
    }
}

// ---------------- 4. fused score + softmax + aggregate (fp16 Q/K/V) ------------
__global__ void aggregate_kernel(const float* __restrict__ rel_pri, int N) {
    int warp = (blockIdx.x * blockDim.x + threadIdx.x) >> 5;
    int lane = threadIdx.x & 31;
    if (warp >= N) return;
    int beg = g_rowptr[warp], end = g_rowptr[warp + 1];

    int h = lane >> 2;
    float pri = rel_pri[h] * 0.25f;

    uint2 qu = *(const uint2*)&g_Qh[warp * DIM + lane * 4];
    float2 q01 = __half22float2(((const __half2*)&qu)[0]);
    float2 q23 = __half22float2(((const __half2*)&qu)[1]);

    float ax0 = 0.f, ay0 = 0.f, az0 = 0.f, aw0 = 0.f, ws0 = 0.f;
    float ax1 = 0.f, ay1 = 0.f, az1 = 0.f, aw1 = 0.f, ws1 = 0.f;

    int p = beg;
    for (; p < end && (p & 3); p++) {
        int sv = g_esrc[p];
        uint2 ku = *(const uint2*)&g_Kh[sv * DIM + lane * 4];
        uint2 vu = *(const uint2*)&g_Vh[sv * DIM + lane * 4];
        float2 k01 = __half22float2(((const __half2*)&ku)[0]);
        float2 k23 = __half22float2(((const __half2*)&ku)[1]);
        float d = q01.x * k01.x + q01.y * k01.y + q23.x * k23.x + q23.y * k23.y;
        d += __shfl_xor_sync(0xffffffffu, d, 1);
        d += __shfl_xor_sync(0xffffffffu, d, 2);
        float w = __expf(d * pri);
        ws0 += w;
        float2 v01 = __half22float2(((const __half2*)&vu)[0]);
        float2 v23 = __half22float2(((const __half2*)&vu)[1]);
        ax0 += w * v01.x; ay0 += w * v01.y; az0 += w * v23.x; aw0 += w * v23.y;
    }
    for (; p + 3 < end; p += 4) {
        int4 s4 = *(const int4*)&g_esrc[p];
        int sv[4] = {s4.x, s4.y, s4.z, s4.w};
        uint2 kk[4], vk[4];
#pragma unroll
        for (int u = 0; u < 4; u++) kk[u] = *(const uint2*)&g_Kh[sv[u] * DIM + lane * 4];
#pragma unroll
        for (int u = 0; u < 4; u++) vk[u] = *(const uint2*)&g_Vh[sv[u] * DIM + lane * 4];

        float d[4];
#pragma unroll
        for (int u = 0; u < 4; u++) {
            float2 k01 = __half22float2(((const __half2*)&kk[u])[0]);
            float2 k23 = __half22float2(((const __half2*)&kk[u])[1]);
            d[u] = q01.x * k01.x + q01.y * k01.y + q23.x * k23.x + q23.y * k23.y;
        }
#pragma unroll
        for (int u = 0; u < 4; u++) d[u] += __shfl_xor_sync(0xffffffffu, d[u], 1);
#pragma unroll
        for (int u = 0; u < 4; u++) d[u] += __shfl_xor_sync(0xffffffffu, d[u], 2);
        float w[4];
#pragma unroll
        for (int u = 0; u < 4; u++) w[u] = __expf(d[u] * pri);
        ws0 += w[0] + w[2];
        ws1 += w[1] + w[3];
#pragma unroll
        for (int u = 0; u < 4; u++) {
            float2 v01 = __half22float2(((const __half2*)&vk[u])[0]);
            float2 v23 = __half22float2(((const __half2*)&vk[u])[1]);
            if (u & 1) {
                ax1 += w[u] * v01.x; ay1 += w[u] * v01.y;
                az1 += w[u] * v23.x; aw1 += w[u] * v23.y;
            } else {
                ax0 += w[u] * v01.x; ay0 += w[u] * v01.y;
                az0 += w[u] * v23.x; aw0 += w[u] * v23.y;
            }
        }
    }
    for (; p < end; p++) {
        int sv = g_esrc[p];
        uint2 ku = *(const uint2*)&g_Kh[sv * DIM + lane * 4];
        uint2 vu = *(const uint2*)&g_Vh[sv * DIM + lane * 4];
        float2 k01 = __half22float2(((const __half2*)&ku)[0]);
        float2 k23 = __half22float2(((const __half2*)&ku)[1]);
        float d = q01.x * k01.x + q01.y * k01.y + q23.x * k23.x + q23.y * k23.y;
        d += __shfl_xor_sync(0xffffffffu, d, 1);
        d += __shfl_xor_sync(0xffffffffu, d, 2);
        float w = __expf(d * pri);
        ws0 += w;
        float2 v01 = __half22float2(((const __half2*)&vu)[0]);
        float2 v23 = __half22float2(((const __half2*)&vu)[1]);
        ax0 += w * v01.x; ay0 += w * v01.y; az0 += w * v23.x; aw0 += w * v23.y;
    }
    float ax = ax0 + ax1, ay = ay0 + ay1, az = az0 + az1, aw = aw0 + aw1;
    float wsum = ws0 + ws1;
    if (beg < end) {
        float inv = 1.f / wsum;
        ax *= inv; ay *= inv; az *= inv; aw *= inv;
    } else {
        ax = ay = az = aw = 0.f;
    }
    *(float4*)&g_T[warp * DIM + lane * 4] = make_float4(ax, ay, az, aw);
}

// ---------------- launch ------------------------------------------------------
extern "C" void kernel_launch(void* const* d_in, const int* in_sizes, int n_in,
                              void* d_out, int out_size) {
    const float* h       = (const float*)d_in[0];
    const int*   src     = (const int*)d_in[1];
    const int*   dst     = (const int*)d_in[2];
    const float* Wk      = (const float*)d_in[3];
    const float* bk      = (const float*)d_in[4];
    const float* Wq      = (const float*)d_in[5];
    const float* bq      = (const float*)d_in[6];
    const float* Wv      = (const float*)d_in[7];
    const float* bv      = (const float*)d_in[8];
    const float* Wa      = (const float*)d_in[9];
    const float* ba      = (const float*)d_in[10];
    const float* rel_att = (const float*)d_in[11];
    const float* rel_msg = (const float*)d_in[12];
    const float* rel_pri = (const float*)d_in[13];
    const float* skip    = (const float*)d_in[14];
    float* out = (float*)d_out;

    int N = in_sizes[0] / DIM;
    int E = in_sizes[1];

    void *pbk_eff, *pbv_eff, *pQh, *pKh, *pVh, *pT;
    cudaGetSymbolAddress(&pbk_eff, g_bk_eff);
    cudaGetSymbolAddress(&pbv_eff, g_bv_eff);
    cudaGetSymbolAddress(&pQh, g_Qh);
    cudaGetSymbolAddress(&pKh, g_Kh);
    cudaGetSymbolAddress(&pVh, g_Vh);
    cudaGetSymbolAddress(&pT, g_T);

    cudaFuncSetAttribute(gemm_wmma, cudaFuncAttributeMaxDynamicSharedMemorySize, SMEM_W_BYTES);

    static cudaStream_t s2 = nullptr;
    static cudaEvent_t evFork = nullptr, evJoin = nullptr;
    if (!s2) {
        cudaStreamCreateWithFlags(&s2, cudaStreamNonBlocking);
        cudaEventCreateWithFlags(&evFork, cudaEventDisableTiming);
        cudaEventCreateWithFlags(&evJoin, cudaEventDisableTiming);
    }

    int gb = (N + 127) / 128;
    int nsb = (N + SCAN_B - 1) / SCAN_B;

    // ---- fork ----
    cudaEventRecord(evFork, 0);
    cudaStreamWaitEvent(s2, evFork, 0);

    // branch B (s2): CSR build (g_count self-resets each run; no zero pass)
    count_kernel<<<(E + 255) / 256, 256, 0, s2>>>(dst, E);
    scan_phase1<<<nsb, SCAN_B, 0, s2>>>(N);
    scan_phase3<<<nsb, SCAN_B, 0, s2>>>(N, E, nsb);
    scatter_kernel<<<(E + 255) / 256, 256, 0, s2>>>(src, dst, E);
    cudaEventRecord(evJoin, s2);

    // branch A (stream 0): fused weight prep + Q/K/V projections
    prep_all<<<(4 * DIM * DIM + 2 * DIM + 255) / 256, 256>>>(Wq, Wk, Wv, Wa, bk, bv, rel_att, rel_msg);
    gemm_wmma<<<gb, 256, SMEM_W_BYTES>>>(h, N, 0, 3,
        bq, (const float*)pbk_eff, (const float*)pbv_eff,
        (float*)pQh, (float*)pKh, (float*)pVh,
        0b111, 0, nullptr, nullptr);

    // ---- join ----
    cudaStreamWaitEvent(0, evJoin, 0);

    // fused edge-score + segment-softmax + weighted aggregation
    aggregate_kernel<<<(N + 7) / 8, 256>>>(rel_pri, N);

    // output projection + sigmoid-skip blend
    gemm_wmma<<<gb, 256, SMEM_W_BYTES>>>((const float*)pT, N, 3, 1,
        ba, nullptr, nullptr,
        out, nullptr, nullptr,
        0, 1, h, skip);
}